// round 5
// baseline (speedup 1.0000x reference)
#include <cuda_runtime.h>

#define NN 512          // batch size
#define DD 128          // feature dim
#define THREADS 512
#define APC 2           // anchors per CTA
#define NCTA (NN / APC) // 256

typedef unsigned long long ull;

__device__ float g_partial[NCTA];
__device__ float g_count[NCTA];
__device__ int   g_done = 0;   // reset by finalizing CTA each launch

// Margin scalar may arrive as float32 or float64 device scalar.
__device__ __forceinline__ float read_margin(const void* p) {
    if (p == nullptr) return 0.2f;
    float f = *(const float*)p;
    if (f == 0.0f) return 0.0f;
    float af = fabsf(f);
    if (af > 1e-20f && af < 1e6f) return f;
    return (float)(*(const double*)p);
}

// Packed f32x2 FMA: d += a*b elementwise on two fp32 lanes (Blackwell PTX).
__device__ __forceinline__ void fma2(ull& d, ull a, ull b) {
    asm("fma.rn.f32x2 %0, %1, %2, %0;" : "+l"(d) : "l"(a), "l"(b));
}
__device__ __forceinline__ float hsum2(ull v) {
    float lo, hi;
    asm("mov.b64 {%0, %1}, %2;" : "=f"(lo), "=f"(hi) : "l"(v));
    return lo + hi;
}
__device__ __forceinline__ ull pack2(float lo, float hi) {
    ull r;
    asm("mov.b64 %0, {%1, %2};" : "=l"(r) : "f"(lo), "f"(hi));
    return r;
}

// ---------------------------------------------------------------------------
// One fused kernel. CTA = 2 consecutive anchors, 512 threads, 2 CTAs/SM
// (regs <= 64 via launch_bounds) -> 32 warps/SM for latency cover.
// Phase A: Gram-identity distance rows; 8 lanes per row; anchors in registers
//          (zero mainloop LDS). Phase B: thread owns negative g = tid.
// Last-arriving CTA does the deterministic fp64 final reduction.
// ---------------------------------------------------------------------------
__global__ void __launch_bounds__(THREADS, 2)
fused_triplet_kernel(const float* __restrict__ x, const int* __restrict__ L32,
                     const void* __restrict__ mp, float* __restrict__ out,
                     int out_size)
{
    __shared__ float         d_s[APC][NN];       // distance rows, 4 KB
    __shared__ unsigned char same_s[APC][NN];    // same-label flags, 1 KB
    __shared__ float         posd[APC][NN];      // compacted d[pos]+margin, 4 KB
    __shared__ int           lab_s[NN];          // 2 KB
    __shared__ int           np_s[APC];
    __shared__ float         wred[THREADS / 32];
    __shared__ int           flag_s;

    const int tid  = threadIdx.x;
    const int lane = tid & 31;
    const int wid  = tid >> 5;
    const int sub  = tid & 7;      // slice within 8-lane row group
    const int grp  = tid >> 3;     // row-group id 0..63
    const int ib   = blockIdx.x * APC;
    const float m  = read_margin(mp);

    // ---- label dtype detect (int64 => odd 32-bit words all zero) ----
    if (tid == 0) flag_s = 0;
    __syncthreads();
    if (tid < 256 && L32[2 * tid + 1] != 0) flag_s = 1;  // benign OR-race

    // ---- hoist anchors (+eps) into registers: 2 anchors x 4 float4 slices ----
    ull xw[APC][4][2];             // 32 registers of anchor data
    #pragma unroll
    for (int a = 0; a < APC; a++) {
        const float4* xa = (const float4*)(x + (ib + a) * DD);
        #pragma unroll
        for (int i = 0; i < 4; i++) {
            float4 w = xa[sub + 8 * i];
            xw[a][i][0] = pack2(w.x + 1e-6f, w.y + 1e-6f);
            xw[a][i][1] = pack2(w.z + 1e-6f, w.w + 1e-6f);
        }
    }
    // ---- anchor norms in-register (identical across groups, deterministic) ----
    float na[APC];
    #pragma unroll
    for (int a = 0; a < APC; a++) {
        ull nacc = 0;
        #pragma unroll
        for (int i = 0; i < 4; i++) {
            fma2(nacc, xw[a][i][0], xw[a][i][0]);
            fma2(nacc, xw[a][i][1], xw[a][i][1]);
        }
        float s = hsum2(nacc);
        #pragma unroll
        for (int o = 1; o <= 4; o <<= 1) s += __shfl_xor_sync(0xffffffffu, s, o);
        na[a] = s;
    }

    __syncthreads();               // flag_s valid
    const int is64 = (flag_s == 0);
    lab_s[tid] = is64 ? L32[2 * tid] : L32[tid];
    __syncthreads();               // lab_s valid

    int La[APC];
    #pragma unroll
    for (int a = 0; a < APC; a++) La[a] = lab_s[ib + a];

    // ---- Phase A: d^2 = na + nb - 2*dot; 8 passes x 64 rows; zero LDS ----
    #pragma unroll
    for (int pass = 0; pass < 8; pass++) {
        const int r = pass * 64 + grp;
        const ulonglong2* xr = (const ulonglong2*)(x + r * DD);
        ull nb = 0, a0 = 0, a1 = 0;
        #pragma unroll
        for (int i = 0; i < 4; i++) {
            ulonglong2 v = xr[sub + 8 * i];   // 128B-contiguous per row group
            fma2(nb, v.x, v.x);         fma2(nb, v.y, v.y);
            fma2(a0, xw[0][i][0], v.x); fma2(a0, xw[0][i][1], v.y);
            fma2(a1, xw[1][i][0], v.x); fma2(a1, xw[1][i][1], v.y);
        }
        float snb = hsum2(nb);
        float s0 = hsum2(a0), s1 = hsum2(a1);
        #pragma unroll
        for (int o = 1; o <= 4; o <<= 1) {    // 8-lane butterfly
            snb += __shfl_xor_sync(0xffffffffu, snb, o);
            s0  += __shfl_xor_sync(0xffffffffu, s0, o);
            s1  += __shfl_xor_sync(0xffffffffu, s1, o);
        }
        if (sub == 0) {
            const int lr = lab_s[r];
            float dots[APC] = {s0, s1};
            #pragma unroll
            for (int a = 0; a < APC; a++) {
                float d2 = fmaf(-2.f, dots[a], na[a] + snb);
                d_s[a][r]    = sqrtf(fmaxf(d2, 0.f));  // clamp self-pair cancel
                same_s[a][r] = (unsigned char)(lr == La[a]);
            }
        }
    }
    __syncthreads();

    // ---- compact positives: warp a compacts anchor a (ballot, fixed order) ----
    if (wid < APC) {
        const int a = wid, self = ib + a;
        int cnt = 0;
        #pragma unroll
        for (int base = 0; base < NN; base += 32) {
            int j = base + lane;
            bool p = same_s[a][j] && (j != self);
            unsigned msk = __ballot_sync(0xffffffffu, p);
            if (p) posd[a][cnt + __popc(msk & ((1u << lane) - 1u))] = d_s[a][j] + m;
            cnt += __popc(msk);
        }
        if (lane == 0) np_s[a] = cnt;
    }
    __syncthreads();

    // ---- Phase B: thread owns candidate negative g = tid ----
    float acc = 0.f;
    #pragma unroll
    for (int a = 0; a < APC; a++) {
        const int np = np_s[a];
        if (!same_s[a][tid]) {
            const float dg = d_s[a][tid];
            float t0 = 0.f, t1 = 0.f;
            int p = 0;
            for (; p + 1 < np; p += 2) {
                t0 += fmaxf(posd[a][p]     - dg, 0.f);
                t1 += fmaxf(posd[a][p + 1] - dg, 0.f);
            }
            if (p < np) t0 += fmaxf(posd[a][p] - dg, 0.f);
            acc += t0 + t1;
        }
    }

    // ---- block reduce (fixed tree) ----
    #pragma unroll
    for (int o = 16; o > 0; o >>= 1) acc += __shfl_xor_sync(0xffffffffu, acc, o);
    if (lane == 0) wred[wid] = acc;
    __syncthreads();
    if (wid == 0) {
        float v = (lane < THREADS / 32) ? wred[lane] : 0.f;
        #pragma unroll
        for (int o = 8; o > 0; o >>= 1) v += __shfl_xor_sync(0xffffffffu, v, o);
        if (lane == 0) {
            g_partial[blockIdx.x] = v;
            float c = 0.f;
            #pragma unroll
            for (int a = 0; a < APC; a++)
                c += (float)np_s[a] * (float)(NN - 1 - np_s[a]);
            g_count[blockIdx.x] = c;
            __threadfence();
            int t = atomicAdd(&g_done, 1);
            flag_s = (t == NCTA - 1) ? 1 : 0;   // am I the last CTA?
        }
    }
    __syncthreads();

    // ---- last CTA: deterministic fp64 final reduction ----
    if (flag_s && wid == 0) {
        double sd = 0.0, sc = 0.0;
        for (int k = lane; k < NCTA; k += 32) {
            sd += (double)g_partial[k];
            sc += (double)g_count[k];
        }
        #pragma unroll
        for (int o = 16; o > 0; o >>= 1) {
            sd += __shfl_xor_sync(0xffffffffu, sd, o);
            sc += __shfl_xor_sync(0xffffffffu, sc, o);
        }
        if (lane == 0) {
            out[0] = (float)(sd / sc);
            for (int k = 1; k < out_size; k++) out[k] = 0.f;
            __threadfence();
            g_done = 0;   // reset for next graph replay
        }
    }
}

extern "C" void kernel_launch(void* const* d_in, const int* in_sizes, int n_in,
                              void* d_out, int out_size) {
    const float* x      = (const float*)d_in[0];
    const int*   labels = (const int*)d_in[1];
    const void*  margin = (n_in >= 3) ? d_in[2] : nullptr;

    fused_triplet_kernel<<<NCTA, THREADS>>>(x, labels, margin,
                                            (float*)d_out, out_size);
}

// round 6
// speedup vs baseline: 1.1092x; 1.1092x over previous
#include <cuda_runtime.h>

#define NN 512          // batch size
#define DD 128          // feature dim
#define THREADS 512
#define APC 4           // anchors per CTA
#define NCTA (NN / APC) // 128
#define NPOS (NN + 4)   // posd row + sentinel pad

typedef unsigned long long ull;

__device__ float g_partial[NCTA];
__device__ float g_count[NCTA];
__device__ int   g_done = 0;   // reset by finalizing CTA each launch

// Margin scalar may arrive as float32 or float64 device scalar.
__device__ __forceinline__ float read_margin(const void* p) {
    if (p == nullptr) return 0.2f;
    float f = *(const float*)p;
    if (f == 0.0f) return 0.0f;
    float af = fabsf(f);
    if (af > 1e-20f && af < 1e6f) return f;
    return (float)(*(const double*)p);
}

// Packed f32x2 ops (Blackwell PTX).
__device__ __forceinline__ void fma2(ull& d, ull a, ull b) {
    asm("fma.rn.f32x2 %0, %1, %2, %0;" : "+l"(d) : "l"(a), "l"(b));
}
__device__ __forceinline__ ull add2(ull a, ull b) {
    ull r;
    asm("add.rn.f32x2 %0, %1, %2;" : "=l"(r) : "l"(a), "l"(b));
    return r;
}
__device__ __forceinline__ float hsum2(ull v) {
    float lo, hi;
    asm("mov.b64 {%0, %1}, %2;" : "=f"(lo), "=f"(hi) : "l"(v));
    return lo + hi;
}
__device__ __forceinline__ ull pack2(float lo, float hi) {
    ull r;
    asm("mov.b64 %0, {%1, %2};" : "=l"(r) : "f"(lo), "f"(hi));
    return r;
}

// ---------------------------------------------------------------------------
// One fused kernel. CTA = 4 consecutive anchors, 512 threads (R4 config).
// Phase A: Gram-identity distance rows; 8 lanes per row; anchors in registers
//          (zero mainloop LDS).
// Phase B: packed f32x2 — 2 positives per iteration, exact relu via
//          0.5*(t + |t|), sentinel-padded posd (no remainder path).
// Last-arriving CTA does the deterministic fp64 final reduction.
// ---------------------------------------------------------------------------
__global__ void __launch_bounds__(THREADS, 1)
fused_triplet_kernel(const float* __restrict__ x, const int* __restrict__ L32,
                     const void* __restrict__ mp, float* __restrict__ out,
                     int out_size)
{
    __shared__ float                  d_s[APC][NN];     // distance rows, 8 KB
    __shared__ unsigned char          same_s[APC][NN];  // same-label flags, 2 KB
    __shared__ __align__(16) float    posd[APC][NPOS];  // compacted d[pos]+m, ~8 KB
    __shared__ int                    lab_s[NN];        // 2 KB
    __shared__ int                    np_s[APC];
    __shared__ float                  wred[THREADS / 32];
    __shared__ int                    flag_s;

    const int tid  = threadIdx.x;
    const int lane = tid & 31;
    const int wid  = tid >> 5;
    const int sub  = tid & 7;      // slice within 8-lane row group
    const int grp  = tid >> 3;     // row-group id 0..63
    const int ib   = blockIdx.x * APC;
    const float m  = read_margin(mp);

    // ---- label dtype detect (int64 => odd 32-bit words all zero) ----
    if (tid == 0) flag_s = 0;
    __syncthreads();
    if (tid < 256 && L32[2 * tid + 1] != 0) flag_s = 1;  // benign OR-race

    // ---- hoist anchors (+eps) into registers: 4 anchors x 4 float4 slices ----
    ull xw[APC][4][2];             // 64 registers of anchor data
    #pragma unroll
    for (int a = 0; a < APC; a++) {
        const float4* xa = (const float4*)(x + (ib + a) * DD);
        #pragma unroll
        for (int i = 0; i < 4; i++) {
            float4 w = xa[sub + 8 * i];
            xw[a][i][0] = pack2(w.x + 1e-6f, w.y + 1e-6f);
            xw[a][i][1] = pack2(w.z + 1e-6f, w.w + 1e-6f);
        }
    }
    // ---- anchor norms in-register (identical across groups, deterministic) ----
    float na[APC];
    #pragma unroll
    for (int a = 0; a < APC; a++) {
        ull nacc = 0;
        #pragma unroll
        for (int i = 0; i < 4; i++) {
            fma2(nacc, xw[a][i][0], xw[a][i][0]);
            fma2(nacc, xw[a][i][1], xw[a][i][1]);
        }
        float s = hsum2(nacc);
        #pragma unroll
        for (int o = 1; o <= 4; o <<= 1) s += __shfl_xor_sync(0xffffffffu, s, o);
        na[a] = s;
    }

    __syncthreads();               // flag_s valid
    const int is64 = (flag_s == 0);
    lab_s[tid] = is64 ? L32[2 * tid] : L32[tid];
    __syncthreads();               // lab_s valid

    int La[APC];
    #pragma unroll
    for (int a = 0; a < APC; a++) La[a] = lab_s[ib + a];

    // ---- Phase A: d^2 = na + nb - 2*dot; 8 passes x 64 rows; zero LDS ----
    #pragma unroll
    for (int pass = 0; pass < 8; pass++) {
        const int r = pass * 64 + grp;
        const ulonglong2* xr = (const ulonglong2*)(x + r * DD);
        ull nb = 0, a0 = 0, a1 = 0, a2 = 0, a3 = 0;
        #pragma unroll
        for (int i = 0; i < 4; i++) {
            ulonglong2 v = xr[sub + 8 * i];   // 128B-contiguous per row group
            fma2(nb, v.x, v.x);         fma2(nb, v.y, v.y);
            fma2(a0, xw[0][i][0], v.x); fma2(a0, xw[0][i][1], v.y);
            fma2(a1, xw[1][i][0], v.x); fma2(a1, xw[1][i][1], v.y);
            fma2(a2, xw[2][i][0], v.x); fma2(a2, xw[2][i][1], v.y);
            fma2(a3, xw[3][i][0], v.x); fma2(a3, xw[3][i][1], v.y);
        }
        float snb = hsum2(nb);
        float s0 = hsum2(a0), s1 = hsum2(a1), s2 = hsum2(a2), s3 = hsum2(a3);
        #pragma unroll
        for (int o = 1; o <= 4; o <<= 1) {    // 8-lane butterfly
            snb += __shfl_xor_sync(0xffffffffu, snb, o);
            s0  += __shfl_xor_sync(0xffffffffu, s0, o);
            s1  += __shfl_xor_sync(0xffffffffu, s1, o);
            s2  += __shfl_xor_sync(0xffffffffu, s2, o);
            s3  += __shfl_xor_sync(0xffffffffu, s3, o);
        }
        if (sub == 0) {
            const int lr = lab_s[r];
            float dots[APC] = {s0, s1, s2, s3};
            #pragma unroll
            for (int a = 0; a < APC; a++) {
                float d2 = fmaf(-2.f, dots[a], na[a] + snb);
                d_s[a][r]    = sqrtf(fmaxf(d2, 0.f));  // clamp self-pair cancel
                same_s[a][r] = (unsigned char)(lr == La[a]);
            }
        }
    }
    __syncthreads();

    // ---- compact positives: warp a compacts anchor a (ballot, fixed order) ----
    if (wid < APC) {
        const int a = wid, self = ib + a;
        int cnt = 0;
        #pragma unroll
        for (int base = 0; base < NN; base += 32) {
            int j = base + lane;
            bool p = same_s[a][j] && (j != self);
            unsigned msk = __ballot_sync(0xffffffffu, p);
            if (p) posd[a][cnt + __popc(msk & ((1u << lane) - 1u))] = d_s[a][j] + m;
            cnt += __popc(msk);
        }
        if (lane < 4) posd[a][cnt + lane] = -1e30f;  // sentinels: exact-0 relu
        if (lane == 0) np_s[a] = cnt;
    }
    __syncthreads();

    // ---- Phase B: thread owns candidate negative g = tid; packed f32x2 ----
    const ull SMASK = 0x7FFFFFFF7FFFFFFFULL;
    const ull HALF2 = pack2(0.5f, 0.5f);
    ull acc2 = 0, acc2b = 0;
    #pragma unroll
    for (int a = 0; a < APC; a++) {
        const int npairs = (np_s[a] + 3) >> 2;   // pairs of pairs (4 terms/iter)
        if (!same_s[a][tid]) {
            const float dg = d_s[a][tid];
            const ull  ndg2 = pack2(-dg, -dg);
            const ull* pv = (const ull*)&posd[a][0];
            for (int q = 0; q < npairs; q++) {
                ull v0 = pv[2 * q];
                ull v1 = pv[2 * q + 1];
                ull t0 = add2(v0, ndg2);
                ull t1 = add2(v1, ndg2);
                ull r0 = add2(t0, t0 & SMASK);   // 2*relu, exact
                ull r1 = add2(t1, t1 & SMASK);
                fma2(acc2,  r0, HALF2);
                fma2(acc2b, r1, HALF2);
            }
        }
    }
    float acc = hsum2(acc2) + hsum2(acc2b);

    // ---- block reduce (fixed tree) ----
    #pragma unroll
    for (int o = 16; o > 0; o >>= 1) acc += __shfl_xor_sync(0xffffffffu, acc, o);
    if (lane == 0) wred[wid] = acc;
    __syncthreads();
    if (wid == 0) {
        float v = (lane < THREADS / 32) ? wred[lane] : 0.f;
        #pragma unroll
        for (int o = 8; o > 0; o >>= 1) v += __shfl_xor_sync(0xffffffffu, v, o);
        if (lane == 0) {
            g_partial[blockIdx.x] = v;
            float c = 0.f;
            #pragma unroll
            for (int a = 0; a < APC; a++)
                c += (float)np_s[a] * (float)(NN - 1 - np_s[a]);
            g_count[blockIdx.x] = c;
            __threadfence();
            int t = atomicAdd(&g_done, 1);
            flag_s = (t == NCTA - 1) ? 1 : 0;   // am I the last CTA?
        }
    }
    __syncthreads();

    // ---- last CTA: deterministic fp64 final reduction ----
    if (flag_s && wid == 0) {
        double sd = 0.0, sc = 0.0;
        for (int k = lane; k < NCTA; k += 32) {
            sd += (double)g_partial[k];
            sc += (double)g_count[k];
        }
        #pragma unroll
        for (int o = 16; o > 0; o >>= 1) {
            sd += __shfl_xor_sync(0xffffffffu, sd, o);
            sc += __shfl_xor_sync(0xffffffffu, sc, o);
        }
        if (lane == 0) {
            out[0] = (float)(sd / sc);
            for (int k = 1; k < out_size; k++) out[k] = 0.f;
            __threadfence();
            g_done = 0;   // reset for next graph replay
        }
    }
}

extern "C" void kernel_launch(void* const* d_in, const int* in_sizes, int n_in,
                              void* d_out, int out_size) {
    const float* x      = (const float*)d_in[0];
    const int*   labels = (const int*)d_in[1];
    const void*  margin = (n_in >= 3) ? d_in[2] : nullptr;

    fused_triplet_kernel<<<NCTA, THREADS>>>(x, labels, margin,
                                            (float*)d_out, out_size);
}